// round 9
// baseline (speedup 1.0000x reference)
#include <cuda_runtime.h>
#include <math.h>

#define B      64
#define T      200
#define Q      4096
#define Q2     (2*Q)
#define TM1    (T-1)            // 199
#define NROW   (B*TM1)          // 12736
#define NPROBE 12               // probe rows s = 16, 32, ..., 192
#define NPW    (B*NPROBE)       // 768 probe warps
#define NPBLK  (NPW/8)          // 96 probe blocks (8 warps each)
#define NSBLK  ((NROW+7)/8)     // 1592 scan blocks (8 rows each)
#define NBLK   (NPBLK+NSBLK)

// Scratch (no device allocation allowed)
__device__ float    g_p[NROW];
__device__ float    g_a[NROW];
__device__ int      g_flag[NROW];
__device__ unsigned g_pb[B];     // bits 0..11 probe-done, bits 16..27 probe-valid
__device__ float    g_lossb[B];
__device__ int      g_count;     // used only by the 64-block epilogue

__device__ __forceinline__ int check4(float4 v, int vi, int f)
{
    if (v.x != 0.0f) f = vi * 4 + 0;
    if (v.y != 0.0f) f = vi * 4 + 1;
    if (v.z != 0.0f) f = vi * 4 + 2;
    if (v.w != 0.0f) f = vi * 4 + 3;
    return f;
}

// Lane 0 records p/a/flag for output row (b, t) given one-hot index j (or -1).
__device__ __forceinline__ void store_row_lane0(const float* __restrict__ pred,
                                                int b, int t, int j, int lane)
{
    if (lane == 0) {
        float p = 0.0f, a = 0.0f;
        int fl = 0;
        if (j >= 0) {
            const int q = j & (Q - 1);
            a  = (j < Q) ? 1.0f : 0.0f;
            p  = __ldg(pred + ((size_t)b * T + t) * (size_t)Q + q);
            fl = 1;
        }
        const int row = b * TM1 + t;
        g_p[row]    = p;
        g_a[row]    = a;
        g_flag[row] = fl;
    }
}

// ---------------------------------------------------------------------------
// Fused kernel. Blocks [0, NPBLK): 8 probe warps (FULL row: 64 float4/lane =
// 2048 float4 = 8192 floats — R8's bug was covering only 1/4 of this).
// Blocks [NPBLK, NBLK): 8 scan warps, one row per warp, 32 chunks of 2 KB
// (2 float4/lane), ballot early-exit, depth-2 prefetch.
// NO gpu-scope fences / release atomics (R4+R6: per-block gpu-release at
// grid >~2k caps the chip at ~2.2 TB/s). Publish via plain atomicOr (L2);
// poll via ld.global.cg, bounded spin + full-scan fallback.
// ---------------------------------------------------------------------------
__global__ __launch_bounds__(256)
void fused_kernel(const float* __restrict__ pred,
                  const float* __restrict__ batch)
{
    const int bid  = blockIdx.x;
    const int warp = threadIdx.x >> 5;
    const int lane = threadIdx.x & 31;

    if (bid < NPBLK) {
        // ---- probe warp: full row, 8 batches of 8 float4/lane, no exit ----
        const int idx = bid * 8 + warp;          // 0..767
        const int b   = idx / NPROBE;
        const int k   = idx % NPROBE;
        const int s   = 16 * (k + 1);
        const float4* __restrict__ base =
            reinterpret_cast<const float4*>(batch + ((size_t)b * T + s) * (size_t)Q2);

        int f = -1;
        #pragma unroll
        for (int h = 0; h < 8; ++h) {            // 8 * 8 * 32 = 2048 float4
            float4 v[8];
            #pragma unroll
            for (int c = 0; c < 8; ++c) v[c] = base[(h * 8 + c) * 32 + lane];
            #pragma unroll
            for (int c = 0; c < 8; ++c) f = check4(v[c], (h * 8 + c) * 32 + lane, f);
        }
        const unsigned m = __ballot_sync(0xffffffffu, f >= 0);
        const int j = m ? __shfl_sync(0xffffffffu, f, __ffs(m) - 1) : -1;

        store_row_lane0(pred, b, s - 1, j, lane);
        if (lane == 0) {
            const unsigned bits = (1u << k) | ((j >= 0) ? (1u << (16 + k)) : 0u);
            atomicOr(&g_pb[b], bits);            // plain L2 publish, no fence
        }
        return;
    }

    // ---- scan warp: one row ----
    const int row = (bid - NPBLK) * 8 + warp;
    if (row >= NROW) return;
    const int b = row / TM1;
    const int t = row % TM1;
    const int s = t + 1;
    if (s <= 192 && (s & 15) == 0) return;       // handled by a probe warp

    // Wait only for probes governing this row: k with 16(k+1) <= s.
    const int kmax = min(s >> 4, NPROBE);
    unsigned v = 0;
    if (kmax > 0) {
        const unsigned need = (1u << kmax) - 1u;
        if (lane == 0) {
            int it = 0;
            do {
                asm volatile("ld.global.cg.u32 %0, [%1];"
                             : "=r"(v) : "l"(&g_pb[b]) : "memory");
                if ((v & need) == need) break;
                __nanosleep(64);
            } while (++it < 20000);
            if ((v & need) != need) v = 0;       // timeout: no info, full scan
        }
        v = __shfl_sync(0xffffffffu, v, 0);
    }

    int ub = 200;
    #pragma unroll
    for (int k = NPROBE - 1; k >= 0; --k)
        if (((v >> k) & 1u) && !((v >> (16 + k)) & 1u)) ub = 16 * (k + 1);

    if (s >= ub) {                               // provably all-zero: no reads
        store_row_lane0(pred, b, t, -1, lane);
        return;
    }

    // Ballot early-exit scan: 32 chunks of 64 float4 (2 KB), depth-2 prefetch.
    // Chunk c = base[c*64 .. c*64+63]; lane holds base[c*64+lane], base[c*64+32+lane].
    const float4* __restrict__ base =
        reinterpret_cast<const float4*>(batch + ((size_t)b * T + s) * (size_t)Q2);

    float4 a0 = base[lane],       a1 = base[32 + lane];        // chunk 0
    float4 b0 = base[64 + lane],  b1 = base[96 + lane];        // chunk 1
    int jfound = -1;
    #pragma unroll 1
    for (int c = 0; c < 32; ++c) {
        float4 n0 = make_float4(0.f, 0.f, 0.f, 0.f);
        float4 n1 = n0;
        if (c + 2 < 32) {                                      // prefetch c+2
            n0 = base[(c + 2) * 64 + lane];
            n1 = base[(c + 2) * 64 + 32 + lane];
        }
        int f = check4(a0, c * 64 + lane, -1);
        f     = check4(a1, c * 64 + 32 + lane, f);
        const unsigned m = __ballot_sync(0xffffffffu, f >= 0);
        if (m) {
            jfound = __shfl_sync(0xffffffffu, f, __ffs(m) - 1);
            break;
        }
        a0 = b0; a1 = b1; b0 = n0; b1 = n1;
    }
    store_row_lane0(pred, b, t, jfound, lane);
}

// ---------------------------------------------------------------------------
// Epilogue, grid=64 (fence/atomic at this scale measured harmless).
// Also resets g_pb for the next graph replay.
// Output layout: [0]=loss, [1..1+N)=p*maskf, [1+N..1+2N)=a*maskf,
//                [1+2N..1+3N)=mask, N = B*TM1.
// ---------------------------------------------------------------------------
__global__ __launch_bounds__(256)
void epilogue_kernel(const int* __restrict__ isTestP,
                     const int* __restrict__ tslP,
                     float* __restrict__ d_out)
{
    const int b   = blockIdx.x;
    const int tid = threadIdx.x;

    float p = 0.0f, a = 0.0f;
    int myLast = -1;
    if (tid < TM1) {
        const int idx = b * TM1 + tid;
        p = g_p[idx];
        a = g_a[idx];
        if (g_flag[idx] > 0) myLast = tid;
    }

    __shared__ int s_i[256];
    s_i[tid] = myLast;
    __syncthreads();
    #pragma unroll
    for (int off = 128; off > 0; off >>= 1) {
        if (tid < off) s_i[tid] = max(s_i[tid], s_i[tid + off]);
        __syncthreads();
    }
    const int last = max(s_i[0], 0);

    int start = 0;
    if (*isTestP) {
        const int length = last + 1;
        const int tsl = *tslP;
        start = (length > tsl) ? (length - tsl) : 0;
    }

    const bool  m     = (tid < TM1) && (tid >= start) && (tid <= last);
    const float maskf = m ? 1.0f : 0.0f;
    const float cnt   = (float)(last - start + 1);

    float bce = 0.0f;
    if (tid < TM1) {
        const float logp = fmaxf(logf(p), -100.0f);
        const float l1mp = fmaxf(log1pf(-p), -100.0f);
        bce = -(a * logp + (1.0f - a) * l1mp);

        const int idx = b * TM1 + tid;
        d_out[1 + idx]            = p * maskf;
        d_out[1 + NROW + idx]     = a * maskf;
        d_out[1 + 2 * NROW + idx] = maskf;
    }

    __shared__ float s_f[256];
    s_f[tid] = bce * maskf;
    __syncthreads();
    #pragma unroll
    for (int off = 128; off > 0; off >>= 1) {
        if (tid < off) s_f[tid] += s_f[tid + off];
        __syncthreads();
    }

    __shared__ bool s_last;
    if (tid == 0) {
        g_lossb[b] = s_f[0] / cnt;
        g_pb[b]    = 0u;                         // reset for next replay
        __threadfence();
        s_last = (atomicAdd(&g_count, 1) == B - 1);
    }
    __syncthreads();

    if (s_last) {
        __shared__ float s2[64];
        if (tid < B) s2[tid] = g_lossb[tid];
        __syncthreads();
        #pragma unroll
        for (int off = 32; off > 0; off >>= 1) {
            if (tid < off) s2[tid] += s2[tid + off];
            __syncthreads();
        }
        if (tid == 0) {
            d_out[0] = s2[0];
            g_count  = 0;                        // reset for next replay
        }
    }
}

extern "C" void kernel_launch(void* const* d_in, const int* in_sizes, int n_in,
                              void* d_out, int out_size)
{
    const float* pred  = (const float*)d_in[0];
    const float* batch = (const float*)d_in[1];
    const int*   isT   = (const int*)d_in[2];
    const int*   tsl   = (const int*)d_in[3];
    float*       out   = (float*)d_out;

    fused_kernel<<<NBLK, 256>>>(pred, batch);
    epilogue_kernel<<<B, 256>>>(isT, tsl, out);
}

// round 10
// speedup vs baseline: 1.3912x; 1.3912x over previous
#include <cuda_runtime.h>
#include <math.h>

#define B      64
#define T      200
#define Q      4096
#define Q2     (2*Q)
#define TM1    (T-1)            // 199
#define NROW   (B*TM1)          // 12736
#define NPROBE 12               // probe rows s = 16, 32, ..., 192
#define NPB    (B*NPROBE)       // 768 probe blocks
#define NBLK   (NPB + NROW)     // 13504 blocks in the fused launch

// Scratch (no device allocation allowed)
__device__ float    g_p[NROW];
__device__ float    g_a[NROW];
__device__ int      g_flag[NROW];
__device__ unsigned g_pb[B];     // bits 0..11 probe-done, bits 16..27 probe-valid
__device__ float    g_lossb[B];
__device__ int      g_count;     // used only by the 64-block epilogue

__device__ __forceinline__ int check4(float4 v, int vi, int f)
{
    if (v.x != 0.0f) f = vi * 4 + 0;
    if (v.y != 0.0f) f = vi * 4 + 1;
    if (v.z != 0.0f) f = vi * 4 + 2;
    if (v.w != 0.0f) f = vi * 4 + 3;
    return f;
}

__device__ __forceinline__ void store_row(const float* __restrict__ pred,
                                          int b, int t, int j)
{
    if (threadIdx.x == 0) {
        float p = 0.0f, a = 0.0f;
        int fl = 0;
        if (j >= 0) {
            const int q = j & (Q - 1);
            a  = (j < Q) ? 1.0f : 0.0f;
            p  = __ldg(pred + ((size_t)b * T + t) * (size_t)Q + q);
            fl = 1;
        }
        const int row = b * TM1 + t;
        g_p[row]    = p;
        g_a[row]    = a;
        g_flag[row] = fl;
    }
}

// ---------------------------------------------------------------------------
// Two-stage row scan: stage 1 reads the first 16 KB (4 float4/thread, MLP=4),
// ONE barrier decides; stage 2 reads the rest only if needed. Short dependency
// chain (2 stages) with >=16 KB in flight — the R9 lesson: keep the window big.
// ---------------------------------------------------------------------------
__device__ __forceinline__ int scan_row2(const float* __restrict__ batch,
                                         int b, int s)
{
    const float4* __restrict__ base =
        reinterpret_cast<const float4*>(batch + ((size_t)b * T + s) * (size_t)Q2);
    const int tid = threadIdx.x;

    __shared__ int s_idx;
    if (tid == 0) s_idx = -1;
    __syncthreads();

    float4 v0 = base[tid];
    float4 v1 = base[256 + tid];
    float4 v2 = base[512 + tid];
    float4 v3 = base[768 + tid];
    int f = -1;
    f = check4(v0, tid, f);
    f = check4(v1, 256 + tid, f);
    f = check4(v2, 512 + tid, f);
    f = check4(v3, 768 + tid, f);
    if (f >= 0) s_idx = f;

    if (!__syncthreads_or(f >= 0)) {
        v0 = base[1024 + tid];
        v1 = base[1280 + tid];
        v2 = base[1536 + tid];
        v3 = base[1792 + tid];
        f = -1;
        f = check4(v0, 1024 + tid, f);
        f = check4(v1, 1280 + tid, f);
        f = check4(v2, 1536 + tid, f);
        f = check4(v3, 1792 + tid, f);
        if (f >= 0) s_idx = f;
        __syncthreads();
    }
    return s_idx;
}

// ---------------------------------------------------------------------------
// Fused kernel: bids [0,768) probe (full row, MLP=8, one barrier), bids
// [768, NBLK) scan (two-stage, partial-info wait).
// NO gpu-scope fences / release atomics (R4+R6: per-block gpu-release at
// grid ~13k caps the chip at ~2.2 TB/s). Publish = plain atomicOr (L2-point);
// poll = ld.global.cg, bounded spin + full-scan fallback (deadlock-free).
// ---------------------------------------------------------------------------
__global__ __launch_bounds__(256)
void fused_kernel(const float* __restrict__ pred,
                  const float* __restrict__ batch)
{
    const int bid = blockIdx.x;
    const int tid = threadIdx.x;

    if (bid < NPB) {
        // ---- probe block ----
        const int b = bid / NPROBE;
        const int k = bid % NPROBE;
        const int s = 16 * (k + 1);
        const float4* __restrict__ base =
            reinterpret_cast<const float4*>(batch + ((size_t)b * T + s) * (size_t)Q2);

        __shared__ int s_idx;
        if (tid == 0) s_idx = -1;
        __syncthreads();

        float4 v[8];
        #pragma unroll
        for (int c = 0; c < 8; ++c) v[c] = base[c * 256 + tid];
        int f = -1;
        #pragma unroll
        for (int c = 0; c < 8; ++c) f = check4(v[c], c * 256 + tid, f);
        if (f >= 0) s_idx = f;
        __syncthreads();

        store_row(pred, b, s - 1, s_idx);
        if (tid == 0) {
            const unsigned bits =
                (1u << k) | ((s_idx >= 0) ? (1u << (16 + k)) : 0u);
            atomicOr(&g_pb[b], bits);            // plain L2 publish, no fence
        }
        return;
    }

    // ---- scan block ----
    const int row = bid - NPB;
    const int b   = row / TM1;
    const int t   = row % TM1;
    const int s   = t + 1;
    if (s <= 192 && (s & 15) == 0) return;       // handled by a probe block

    // Partial-info wait: only probes k with 16(k+1) <= s govern this row.
    const int kmax = min(s >> 4, NPROBE);
    unsigned v = 0;
    if (kmax > 0) {
        const unsigned need = (1u << kmax) - 1u;
        __shared__ unsigned s_v;
        if (tid == 0) {
            unsigned w = 0;
            int it = 0;
            do {
                asm volatile("ld.global.cg.u32 %0, [%1];"
                             : "=r"(w) : "l"(&g_pb[b]) : "memory");
                if ((w & need) == need) break;
                __nanosleep(64);
            } while (++it < 20000);
            s_v = ((w & need) == need) ? w : 0u; // timeout => no info
        }
        __syncthreads();
        v = s_v;
    }

    int ub = 200;
    #pragma unroll
    for (int k = NPROBE - 1; k >= 0; --k)
        if (((v >> k) & 1u) && !((v >> (16 + k)) & 1u)) ub = 16 * (k + 1);

    if (s >= ub) {                               // provably all-zero: no reads
        store_row(pred, b, t, -1);
        return;
    }
    const int j = scan_row2(batch, b, s);
    store_row(pred, b, t, j);
}

// ---------------------------------------------------------------------------
// Epilogue, grid=64. Also resets g_pb for the next graph replay.
// Output layout: [0]=loss, [1..1+N)=p*maskf, [1+N..1+2N)=a*maskf,
//                [1+2N..1+3N)=mask, N = B*TM1.
// ---------------------------------------------------------------------------
__global__ __launch_bounds__(256)
void epilogue_kernel(const int* __restrict__ isTestP,
                     const int* __restrict__ tslP,
                     float* __restrict__ d_out)
{
    const int b   = blockIdx.x;
    const int tid = threadIdx.x;

    float p = 0.0f, a = 0.0f;
    int myLast = -1;
    if (tid < TM1) {
        const int idx = b * TM1 + tid;
        p = g_p[idx];
        a = g_a[idx];
        if (g_flag[idx] > 0) myLast = tid;
    }

    __shared__ int s_i[256];
    s_i[tid] = myLast;
    __syncthreads();
    #pragma unroll
    for (int off = 128; off > 0; off >>= 1) {
        if (tid < off) s_i[tid] = max(s_i[tid], s_i[tid + off]);
        __syncthreads();
    }
    const int last = max(s_i[0], 0);

    int start = 0;
    if (*isTestP) {
        const int length = last + 1;
        const int tsl = *tslP;
        start = (length > tsl) ? (length - tsl) : 0;
    }

    const bool  m     = (tid < TM1) && (tid >= start) && (tid <= last);
    const float maskf = m ? 1.0f : 0.0f;
    const float cnt   = (float)(last - start + 1);

    float bce = 0.0f;
    if (tid < TM1) {
        const float logp = fmaxf(logf(p), -100.0f);
        const float l1mp = fmaxf(log1pf(-p), -100.0f);
        bce = -(a * logp + (1.0f - a) * l1mp);

        const int idx = b * TM1 + tid;
        d_out[1 + idx]            = p * maskf;
        d_out[1 + NROW + idx]     = a * maskf;
        d_out[1 + 2 * NROW + idx] = maskf;
    }

    __shared__ float s_f[256];
    s_f[tid] = bce * maskf;
    __syncthreads();
    #pragma unroll
    for (int off = 128; off > 0; off >>= 1) {
        if (tid < off) s_f[tid] += s_f[tid + off];
        __syncthreads();
    }

    __shared__ bool s_last;
    if (tid == 0) {
        g_lossb[b] = s_f[0] / cnt;
        g_pb[b]    = 0u;                         // reset for next replay
        __threadfence();
        s_last = (atomicAdd(&g_count, 1) == B - 1);
    }
    __syncthreads();

    if (s_last) {
        __shared__ float s2[64];
        if (tid < B) s2[tid] = g_lossb[tid];
        __syncthreads();
        #pragma unroll
        for (int off = 32; off > 0; off >>= 1) {
            if (tid < off) s2[tid] += s2[tid + off];
            __syncthreads();
        }
        if (tid == 0) {
            d_out[0] = s2[0];
            g_count  = 0;                        // reset for next replay
        }
    }
}

extern "C" void kernel_launch(void* const* d_in, const int* in_sizes, int n_in,
                              void* d_out, int out_size)
{
    const float* pred  = (const float*)d_in[0];
    const float* batch = (const float*)d_in[1];
    const int*   isT   = (const int*)d_in[2];
    const int*   tsl   = (const int*)d_in[3];
    float*       out   = (float*)d_out;

    fused_kernel<<<NBLK, 256>>>(pred, batch);
    epilogue_kernel<<<B, 256>>>(isT, tsl, out);
}

// round 11
// speedup vs baseline: 1.4590x; 1.0487x over previous
#include <cuda_runtime.h>
#include <math.h>

#define B      64
#define T      200
#define Q      4096
#define Q2     (2*Q)
#define TM1    (T-1)            // 199
#define NROW   (B*TM1)          // 12736
#define NPROBE 12               // probe rows s = 16, 32, ..., 192
#define NPB    (B*NPROBE)       // 768 probe blocks
#define NBLK   (NPB + NROW)     // 13504 blocks in the fused launch

// Scratch (no device allocation allowed)
__device__ float    g_p[NROW];
__device__ float    g_a[NROW];
__device__ int      g_flag[NROW];
__device__ unsigned g_pb[B];     // bits 0..11 probe-done, bits 16..27 probe-valid
__device__ float    g_lossb[B];
__device__ int      g_count;     // used only by the 64-block epilogue

__device__ __forceinline__ int check4(float4 v, int vi, int f)
{
    if (v.x != 0.0f) f = vi * 4 + 0;
    if (v.y != 0.0f) f = vi * 4 + 1;
    if (v.z != 0.0f) f = vi * 4 + 2;
    if (v.w != 0.0f) f = vi * 4 + 3;
    return f;
}

__device__ __forceinline__ void store_row(const float* __restrict__ pred,
                                          int b, int t, int j)
{
    if (threadIdx.x == 0) {
        float p = 0.0f, a = 0.0f;
        int fl = 0;
        if (j >= 0) {
            const int q = j & (Q - 1);
            a  = (j < Q) ? 1.0f : 0.0f;
            p  = __ldg(pred + ((size_t)b * T + t) * (size_t)Q + q);
            fl = 1;
        }
        const int row = b * TM1 + t;
        g_p[row]    = p;
        g_a[row]    = a;
        g_flag[row] = fl;
    }
}

// ---------------------------------------------------------------------------
// Three-stage row scan: 16 KB / 8 KB / 8 KB. E[bytes] = 22 KB for a uniform
// one-hot vs 24 KB for the 16/16 split; keeps >=8 KB in flight per stage
// (R9 lesson: window must stay large).
// ---------------------------------------------------------------------------
__device__ __forceinline__ int scan_row3(const float* __restrict__ batch,
                                         int b, int s)
{
    const float4* __restrict__ base =
        reinterpret_cast<const float4*>(batch + ((size_t)b * T + s) * (size_t)Q2);
    const int tid = threadIdx.x;

    __shared__ int s_idx;
    if (tid == 0) s_idx = -1;
    __syncthreads();

    // Stage A: float4 [0, 1024)
    {
        float4 v0 = base[tid];
        float4 v1 = base[256 + tid];
        float4 v2 = base[512 + tid];
        float4 v3 = base[768 + tid];
        int f = -1;
        f = check4(v0, tid, f);
        f = check4(v1, 256 + tid, f);
        f = check4(v2, 512 + tid, f);
        f = check4(v3, 768 + tid, f);
        if (f >= 0) s_idx = f;
        if (__syncthreads_or(f >= 0)) return s_idx;
    }
    // Stage B: float4 [1024, 1536)
    {
        float4 v0 = base[1024 + tid];
        float4 v1 = base[1280 + tid];
        int f = -1;
        f = check4(v0, 1024 + tid, f);
        f = check4(v1, 1280 + tid, f);
        if (f >= 0) s_idx = f;
        if (__syncthreads_or(f >= 0)) return s_idx;
    }
    // Stage C: float4 [1536, 2048)
    {
        float4 v0 = base[1536 + tid];
        float4 v1 = base[1792 + tid];
        int f = -1;
        f = check4(v0, 1536 + tid, f);
        f = check4(v1, 1792 + tid, f);
        if (f >= 0) s_idx = f;
        __syncthreads();
    }
    return s_idx;
}

// ---------------------------------------------------------------------------
// Fused kernel: bids [0,768) probe; bids [768, NBLK) scan, t-MAJOR order
// (wave 1 = small-s rows of all batches: no probe dependency, ~all valid).
// NO gpu-scope fences / release atomics (R4+R6: per-block gpu-release at
// grid ~13k caps the chip at ~2.2 TB/s). Publish = plain atomicOr (L2-point);
// poll = ld.global.cg, bounded spin + full-scan fallback (deadlock-free).
// ---------------------------------------------------------------------------
__global__ __launch_bounds__(256)
void fused_kernel(const float* __restrict__ pred,
                  const float* __restrict__ batch)
{
    const int bid = blockIdx.x;
    const int tid = threadIdx.x;

    if (bid < NPB) {
        // ---- probe block: full row, MLP=8, one barrier ----
        const int b = bid / NPROBE;
        const int k = bid % NPROBE;
        const int s = 16 * (k + 1);
        const float4* __restrict__ base =
            reinterpret_cast<const float4*>(batch + ((size_t)b * T + s) * (size_t)Q2);

        __shared__ int s_idx;
        if (tid == 0) s_idx = -1;
        __syncthreads();

        float4 v[8];
        #pragma unroll
        for (int c = 0; c < 8; ++c) v[c] = base[c * 256 + tid];
        int f = -1;
        #pragma unroll
        for (int c = 0; c < 8; ++c) f = check4(v[c], c * 256 + tid, f);
        if (f >= 0) s_idx = f;
        __syncthreads();

        store_row(pred, b, s - 1, s_idx);
        if (tid == 0) {
            const unsigned bits =
                (1u << k) | ((s_idx >= 0) ? (1u << (16 + k)) : 0u);
            atomicOr(&g_pb[b], bits);            // plain L2 publish, no fence
        }
        return;
    }

    // ---- scan block (t-major: consecutive bids sweep all batches at one t) ----
    const int sb = bid - NPB;                    // 0 .. NROW-1
    const int t  = sb / B;                       // 0 .. 198
    const int b  = sb % B;
    const int s  = t + 1;
    if (s <= 192 && (s & 15) == 0) return;       // handled by a probe block

    // Partial-info wait: only probes k with 16(k+1) <= s govern this row.
    const int kmax = min(s >> 4, NPROBE);
    unsigned v = 0;
    if (kmax > 0) {
        const unsigned need = (1u << kmax) - 1u;
        __shared__ unsigned s_v;
        if (tid == 0) {
            unsigned w = 0;
            int it = 0;
            do {
                asm volatile("ld.global.cg.u32 %0, [%1];"
                             : "=r"(w) : "l"(&g_pb[b]) : "memory");
                if ((w & need) == need) break;
                __nanosleep(64);
            } while (++it < 20000);
            s_v = ((w & need) == need) ? w : 0u; // timeout => no info
        }
        __syncthreads();
        v = s_v;
    }

    int ub = 200;
    #pragma unroll
    for (int k = NPROBE - 1; k >= 0; --k)
        if (((v >> k) & 1u) && !((v >> (16 + k)) & 1u)) ub = 16 * (k + 1);

    if (s >= ub) {                               // provably all-zero: no reads
        store_row(pred, b, t, -1);
        return;
    }
    const int j = scan_row3(batch, b, s);
    store_row(pred, b, t, j);
}

// ---------------------------------------------------------------------------
// Epilogue, grid=64, launched with PDL (programmatic stream serialization):
// it may be scheduled while fused_kernel drains; griddepcontrol.wait blocks
// until the fused kernel completes (which also orders its memory).
// Output layout: [0]=loss, [1..1+N)=p*maskf, [1+N..1+2N)=a*maskf,
//                [1+2N..1+3N)=mask, N = B*TM1.
// ---------------------------------------------------------------------------
__global__ __launch_bounds__(256)
void epilogue_kernel(const int* __restrict__ isTestP,
                     const int* __restrict__ tslP,
                     float* __restrict__ d_out)
{
    asm volatile("griddepcontrol.wait;" ::: "memory");   // wait for fused_kernel

    const int b   = blockIdx.x;
    const int tid = threadIdx.x;

    float p = 0.0f, a = 0.0f;
    int myLast = -1;
    if (tid < TM1) {
        const int idx = b * TM1 + tid;
        p = g_p[idx];
        a = g_a[idx];
        if (g_flag[idx] > 0) myLast = tid;
    }

    __shared__ int s_i[256];
    s_i[tid] = myLast;
    __syncthreads();
    #pragma unroll
    for (int off = 128; off > 0; off >>= 1) {
        if (tid < off) s_i[tid] = max(s_i[tid], s_i[tid + off]);
        __syncthreads();
    }
    const int last = max(s_i[0], 0);

    int start = 0;
    if (*isTestP) {
        const int length = last + 1;
        const int tsl = *tslP;
        start = (length > tsl) ? (length - tsl) : 0;
    }

    const bool  m     = (tid < TM1) && (tid >= start) && (tid <= last);
    const float maskf = m ? 1.0f : 0.0f;
    const float cnt   = (float)(last - start + 1);

    float bce = 0.0f;
    if (tid < TM1) {
        const float logp = fmaxf(logf(p), -100.0f);
        const float l1mp = fmaxf(log1pf(-p), -100.0f);
        bce = -(a * logp + (1.0f - a) * l1mp);

        const int idx = b * TM1 + tid;
        d_out[1 + idx]            = p * maskf;
        d_out[1 + NROW + idx]     = a * maskf;
        d_out[1 + 2 * NROW + idx] = maskf;
    }

    __shared__ float s_f[256];
    s_f[tid] = bce * maskf;
    __syncthreads();
    #pragma unroll
    for (int off = 128; off > 0; off >>= 1) {
        if (tid < off) s_f[tid] += s_f[tid + off];
        __syncthreads();
    }

    __shared__ bool s_last;
    if (tid == 0) {
        g_lossb[b] = s_f[0] / cnt;
        g_pb[b]    = 0u;                         // reset for next replay
        __threadfence();
        s_last = (atomicAdd(&g_count, 1) == B - 1);
    }
    __syncthreads();

    if (s_last) {
        __shared__ float s2[64];
        if (tid < B) s2[tid] = g_lossb[tid];
        __syncthreads();
        #pragma unroll
        for (int off = 32; off > 0; off >>= 1) {
            if (tid < off) s2[tid] += s2[tid + off];
            __syncthreads();
        }
        if (tid == 0) {
            d_out[0] = s2[0];
            g_count  = 0;                        // reset for next replay
        }
    }
}

extern "C" void kernel_launch(void* const* d_in, const int* in_sizes, int n_in,
                              void* d_out, int out_size)
{
    const float* pred  = (const float*)d_in[0];
    const float* batch = (const float*)d_in[1];
    const int*   isT   = (const int*)d_in[2];
    const int*   tsl   = (const int*)d_in[3];
    float*       out   = (float*)d_out;

    fused_kernel<<<NBLK, 256>>>(pred, batch);

    // Epilogue with programmatic dependent launch: overlaps its launch/setup
    // with the fused kernel's tail; griddepcontrol.wait provides the sync.
    cudaLaunchConfig_t cfg = {};
    cfg.gridDim  = dim3(B, 1, 1);
    cfg.blockDim = dim3(256, 1, 1);
    cfg.stream   = 0;
    cudaLaunchAttribute attr[1];
    attr[0].id = cudaLaunchAttributeProgrammaticStreamSerialization;
    attr[0].val.programmaticStreamSerializationAllowed = 1;
    cfg.attrs    = attr;
    cfg.numAttrs = 1;
    cudaLaunchKernelEx(&cfg, epilogue_kernel, isT, tsl, out);
}